// round 1
// baseline (speedup 1.0000x reference)
#include <cuda_runtime.h>
#include <math.h>

#define Vn 10000
#define Dn 300
#define Bn 64
#define Ln 128
#define CFc 5.0f
#define EPSc 1e-8f

// ------- scratch (device globals; no allocation allowed) -------
__device__ float g_per[Bn * Dn];          // per-sample means
__device__ float g_ctx[Dn];               // context vector
__device__ float g_cn;                    // |context|
__device__ float g_A[Vn];                 // 5*lam[v]*cos[v]
__device__ float g_Bc[Vn];                // 5*(1-lam[v])*aff[v]
__device__ int   g_flag[Vn];              // concept used?
__device__ float g_invZ[Vn];              // 1/sum(exp(w)) per concept row
__device__ float g_Pt[(size_t)Vn * Bn];   // P transposed: [V][B]

// ------- K0: zero flags + output -------
__global__ void k_zero(float* __restrict__ out) {
    int i = blockIdx.x * blockDim.x + threadIdx.x;
    if (i < Vn) g_flag[i] = 0;
    if (i < Bn * Dn) out[i] = 0.0f;
}

// ------- K1: per-sample ragged mean of embed rows -------
__global__ void k_context(const int* __restrict__ list,
                          const int* __restrict__ lens,
                          const float* __restrict__ embed) {
    int b = blockIdx.x;
    int len = lens[b];
    int t = threadIdx.x;  // 128 threads
    float a0 = 0.f, a1 = 0.f, a2 = 0.f;
    for (int l = 0; l < len; l++) {
        const float* row = embed + (size_t)list[b * Ln + l] * Dn;
        a0 += row[t];
        a1 += row[t + 128];
        if (t + 256 < Dn) a2 += row[t + 256];
    }
    float inv = 1.0f / (float)(len > 0 ? len : 1);
    g_per[b * Dn + t] = a0 * inv;
    g_per[b * Dn + t + 128] = a1 * inv;
    if (t + 256 < Dn) g_per[b * Dn + t + 256] = a2 * inv;
}

// ------- K2: reduce over batch to context, compute its norm -------
__global__ void k_reduce_ctx() {
    __shared__ float sred[512];
    int d = threadIdx.x;  // 512 threads
    float c = 0.f;
    if (d < Dn) {
        float s = 0.f;
        for (int b = 0; b < Bn; b++) s += g_per[b * Dn + d];
        c = s * (1.0f / (float)Bn);
        g_ctx[d] = c;
    }
    sred[d] = c * c;
    __syncthreads();
    for (int s = 256; s > 0; s >>= 1) {
        if (d < s) sred[d] += sred[d + s];
        __syncthreads();
    }
    if (d == 0) g_cn = sqrtf(sred[0]);
}

// ------- K3: per-concept cos-sim -> A[v], B[v] (one warp per row) -------
__global__ void k_ab(const float* __restrict__ cw,
                     const float* __restrict__ aff,
                     const float* __restrict__ lam) {
    __shared__ float sctx[Dn];
    for (int i = threadIdx.x; i < Dn; i += 256) sctx[i] = g_ctx[i];
    __syncthreads();
    int w = threadIdx.x >> 5, lane = threadIdx.x & 31;
    int v = blockIdx.x * 8 + w;
    if (v >= Vn) return;
    const float* row = cw + (size_t)v * Dn;
    float dot = 0.f, nn = 0.f;
    for (int d = lane; d < Dn; d += 32) {
        float x = row[d];
        dot += x * sctx[d];
        nn += x * x;
    }
    for (int o = 16; o > 0; o >>= 1) {
        dot += __shfl_xor_sync(0xffffffffu, dot, o);
        nn  += __shfl_xor_sync(0xffffffffu, nn, o);
    }
    if (lane == 0) {
        float cosv = fabsf(dot) / fmaxf(g_cn * sqrtf(nn), EPSc);
        float la = lam[v];
        g_A[v]  = CFc * la * cosv;
        g_Bc[v] = CFc * (1.0f - la) * aff[v];
    }
}

// ------- K4: flag used concepts (valid positions only) -------
__global__ void k_flag(const int* __restrict__ list,
                       const int* __restrict__ lens) {
    int i = blockIdx.x * blockDim.x + threadIdx.x;
    if (i >= Bn * Ln) return;
    int b = i / Ln, l = i % Ln;
    if (l < lens[b]) g_flag[list[i]] = 1;
}

// ------- K5: softmax denominators per used concept row -------
// weights bounded in [0, ~10] after *CF, so no max-subtraction needed.
__global__ void k_z(const float* __restrict__ edge) {
    int c = blockIdx.x;
    if (!g_flag[c]) return;
    const float* row = edge + (size_t)c * Vn;
    float s = 0.f;
    for (int v = threadIdx.x; v < Vn; v += 256) {
        float em = row[v];
        float w = em * g_A[v] + (em > 0.f ? g_Bc[v] : 0.f);
        s += __expf(w);
    }
    __shared__ float sr[256];
    sr[threadIdx.x] = s;
    __syncthreads();
    for (int st = 128; st > 0; st >>= 1) {
        if (threadIdx.x < st) sr[threadIdx.x] += sr[threadIdx.x + st];
        __syncthreads();
    }
    if (threadIdx.x == 0) g_invZ[c] = 1.0f / sr[0];
}

// ------- K6: accumulate P_t[v][b] = sum_l softmax_row(c_bl)[v] / denom_b -------
// grid (ceil(V/1024), B), block 128, 8 v-elements per thread in registers.
__global__ void k_p(const int* __restrict__ list,
                    const int* __restrict__ lens,
                    const float* __restrict__ edge) {
    int b = blockIdx.y;
    int v0 = blockIdx.x * 1024;
    int t = threadIdx.x;
    float a[8], bb[8], acc[8];
#pragma unroll
    for (int j = 0; j < 8; j++) {
        int v = v0 + j * 128 + t;
        bool ok = v < Vn;
        a[j]  = ok ? g_A[v]  : 0.f;
        bb[j] = ok ? g_Bc[v] : 0.f;
        acc[j] = 0.f;
    }
    int len = lens[b];
    for (int l = 0; l < len; l++) {
        int c = list[b * Ln + l];
        float iz = g_invZ[c];
        const float* row = edge + (size_t)c * Vn + v0;
#pragma unroll
        for (int j = 0; j < 8; j++) {
            int idx = j * 128 + t;
            if (v0 + idx < Vn) {
                float em = row[idx];
                float w = em * a[j] + (em > 0.f ? bb[j] : 0.f);
                acc[j] += __expf(w) * iz;
            }
        }
    }
    float invd = 1.0f / (float)(len > 0 ? len : 1);
#pragma unroll
    for (int j = 0; j < 8; j++) {
        int v = v0 + j * 128 + t;
        if (v < Vn) g_Pt[(size_t)v * Bn + b] = acc[j] * invd;
    }
}

// ------- K7: out[B,300] = P[B,V] @ W[V,300], K-split + atomics -------
#define KT 32
#define DT 32
#define KSPLIT 16
#define KCHUNK 625  // ceil(10000/16)
__global__ void k_out(const float* __restrict__ cw, float* __restrict__ out) {
    int d0 = blockIdx.x * DT;
    int kbeg = blockIdx.y * KCHUNK;
    int kend = min(kbeg + KCHUNK, Vn);
    __shared__ float sP[KT][Bn + 4];
    __shared__ float sW[KT][DT + 4];
    int t = threadIdx.x;     // 128 threads
    int tb = t & 15;         // b quad: rows tb*4 .. tb*4+3
    int td = t >> 4;         // d quad: cols d0+td*4 .. +3
    float acc[4][4];
#pragma unroll
    for (int i = 0; i < 4; i++)
#pragma unroll
        for (int j = 0; j < 4; j++) acc[i][j] = 0.f;

    for (int k0 = kbeg; k0 < kend; k0 += KT) {
        for (int i = t; i < KT * Bn; i += 128) {
            int kk = i / Bn, b = i % Bn;
            int kv = k0 + kk;
            sP[kk][b] = (kv < kend) ? g_Pt[(size_t)kv * Bn + b] : 0.f;
        }
        for (int i = t; i < KT * DT; i += 128) {
            int kk = i / DT, j = i % DT;
            int kv = k0 + kk, d = d0 + j;
            sW[kk][j] = (kv < kend && d < Dn) ? cw[(size_t)kv * Dn + d] : 0.f;
        }
        __syncthreads();
#pragma unroll 8
        for (int k = 0; k < KT; k++) {
            float p0 = sP[k][tb * 4], p1 = sP[k][tb * 4 + 1];
            float p2 = sP[k][tb * 4 + 2], p3 = sP[k][tb * 4 + 3];
            float w0 = sW[k][td * 4], w1 = sW[k][td * 4 + 1];
            float w2 = sW[k][td * 4 + 2], w3 = sW[k][td * 4 + 3];
            acc[0][0] += p0 * w0; acc[0][1] += p0 * w1; acc[0][2] += p0 * w2; acc[0][3] += p0 * w3;
            acc[1][0] += p1 * w0; acc[1][1] += p1 * w1; acc[1][2] += p1 * w2; acc[1][3] += p1 * w3;
            acc[2][0] += p2 * w0; acc[2][1] += p2 * w1; acc[2][2] += p2 * w2; acc[2][3] += p2 * w3;
            acc[3][0] += p3 * w0; acc[3][1] += p3 * w1; acc[3][2] += p3 * w2; acc[3][3] += p3 * w3;
        }
        __syncthreads();
    }
#pragma unroll
    for (int i = 0; i < 4; i++) {
        int b = tb * 4 + i;
#pragma unroll
        for (int j = 0; j < 4; j++) {
            int d = d0 + td * 4 + j;
            if (d < Dn) atomicAdd(&out[b * Dn + d], acc[i][j]);
        }
    }
}

extern "C" void kernel_launch(void* const* d_in, const int* in_sizes, int n_in,
                              void* d_out, int out_size) {
    const int*   list  = (const int*)d_in[0];
    const int*   lens  = (const int*)d_in[1];
    const float* embed = (const float*)d_in[2];
    const float* cw    = (const float*)d_in[3];
    const float* edge  = (const float*)d_in[4];
    const float* aff   = (const float*)d_in[5];
    const float* lam   = (const float*)d_in[6];
    float* out = (float*)d_out;

    k_zero<<<75, 256>>>(out);                       // 75*256 = 19200 covers both
    k_context<<<Bn, 128>>>(list, lens, embed);
    k_reduce_ctx<<<1, 512>>>();
    k_ab<<<(Vn + 7) / 8, 256>>>(cw, aff, lam);
    k_flag<<<(Bn * Ln + 255) / 256, 256>>>(list, lens);
    k_z<<<Vn, 256>>>(edge);
    k_p<<<dim3((Vn + 1023) / 1024, Bn), 128>>>(list, lens, edge);
    k_out<<<dim3((Dn + DT - 1) / DT, KSPLIT), 128>>>(cw, out);
}

// round 4
// speedup vs baseline: 1.5269x; 1.5269x over previous
#include <cuda_runtime.h>
#include <math.h>

#define Vn 10000
#define Dn 300
#define Bn 64
#define Ln 128
#define CFc 5.0f
#define EPSc 1e-8f

// ------- scratch (device globals; no allocation allowed) -------
__device__ float g_per[Bn * Dn];          // per-sample means
__device__ float g_ctx[Dn];               // context vector
__device__ float g_cn;                    // |context|
__device__ float g_A[Vn];                 // 5*lam[v]*cos[v]
__device__ float g_Bc[Vn];                // 5*(1-lam[v])*aff[v]
__device__ int   g_flag[Vn];              // concept used?
__device__ float g_invZ[Vn];              // 1/sum(exp(w)) per concept row
__device__ float g_Pt[(size_t)Bn * Vn];   // P: [B][V] (contiguous per-b)

// ------- K0: zero flags + output -------
__global__ void k_zero(float* __restrict__ out) {
    int i = blockIdx.x * blockDim.x + threadIdx.x;
    if (i < Vn) g_flag[i] = 0;
    if (i < Bn * Dn) out[i] = 0.0f;
}

// ------- K1: per-sample ragged mean of embed rows (token-parallel) -------
// 512 threads: comp = t%128 (float4 idx, <75 active), grp = t/128 (4 token groups)
__global__ void k_context(const int* __restrict__ list,
                          const int* __restrict__ lens,
                          const float* __restrict__ embed) {
    __shared__ float4 sacc[4][80];
    int b = blockIdx.x;
    int len = lens[b];
    int t = threadIdx.x;
    int comp = t & 127;
    int grp = t >> 7;
    float4 acc = make_float4(0.f, 0.f, 0.f, 0.f);
    if (comp < 75) {
        for (int l = grp; l < len; l += 4) {
            const float4* row = (const float4*)(embed + (size_t)list[b * Ln + l] * Dn);
            float4 x = row[comp];
            acc.x += x.x; acc.y += x.y; acc.z += x.z; acc.w += x.w;
        }
        sacc[grp][comp] = acc;
    }
    __syncthreads();
    if (grp == 0 && comp < 75) {
        float4 s = sacc[0][comp];
#pragma unroll
        for (int g = 1; g < 4; g++) {
            float4 x = sacc[g][comp];
            s.x += x.x; s.y += x.y; s.z += x.z; s.w += x.w;
        }
        float inv = 1.0f / (float)(len > 0 ? len : 1);
        s.x *= inv; s.y *= inv; s.z *= inv; s.w *= inv;
        ((float4*)(g_per + (size_t)b * Dn))[comp] = s;
    }
}

// ------- K2: reduce over batch to context, compute its norm -------
__global__ void k_reduce_ctx() {
    __shared__ float sred[512];
    int d = threadIdx.x;  // 512 threads
    float c = 0.f;
    if (d < Dn) {
        float s = 0.f;
        for (int b = 0; b < Bn; b++) s += g_per[b * Dn + d];
        c = s * (1.0f / (float)Bn);
        g_ctx[d] = c;
    }
    sred[d] = c * c;
    __syncthreads();
    for (int s = 256; s > 0; s >>= 1) {
        if (d < s) sred[d] += sred[d + s];
        __syncthreads();
    }
    if (d == 0) g_cn = sqrtf(sred[0]);
}

// ------- K3: per-concept cos-sim -> A[v], B[v] (one warp per row, float4) -------
__global__ void k_ab(const float* __restrict__ cw,
                     const float* __restrict__ aff,
                     const float* __restrict__ lam) {
    __shared__ float4 sctx[75];
    for (int i = threadIdx.x; i < 75; i += 256)
        sctx[i] = ((const float4*)g_ctx)[i];
    __syncthreads();
    int w = threadIdx.x >> 5, lane = threadIdx.x & 31;
    int v = blockIdx.x * 8 + w;
    if (v >= Vn) return;
    const float4* row = (const float4*)(cw + (size_t)v * Dn);  // 75 float4
    float dot = 0.f, nn = 0.f;
#pragma unroll
    for (int i = 0; i < 3; i++) {
        int idx = lane + i * 32;
        if (idx < 75) {
            float4 x = row[idx];
            float4 c = sctx[idx];
            dot += x.x * c.x + x.y * c.y + x.z * c.z + x.w * c.w;
            nn  += x.x * x.x + x.y * x.y + x.z * x.z + x.w * x.w;
        }
    }
#pragma unroll
    for (int o = 16; o > 0; o >>= 1) {
        dot += __shfl_xor_sync(0xffffffffu, dot, o);
        nn  += __shfl_xor_sync(0xffffffffu, nn, o);
    }
    if (lane == 0) {
        float cosv = fabsf(dot) / fmaxf(g_cn * sqrtf(nn), EPSc);
        float la = lam[v];
        g_A[v]  = CFc * la * cosv;
        g_Bc[v] = CFc * (1.0f - la) * aff[v];
    }
}

// ------- K4: flag used concepts (valid positions only) -------
__global__ void k_flag(const int* __restrict__ list,
                       const int* __restrict__ lens) {
    int i = blockIdx.x * blockDim.x + threadIdx.x;
    if (i >= Bn * Ln) return;
    int b = i / Ln, l = i % Ln;
    if (l < lens[b]) g_flag[list[i]] = 1;
}

// ------- K5: softmax denominators per used concept row -------
// float4 strips, 2-deep software pipeline for guaranteed MLP.
// weights bounded in [0, ~10] after *CF, so no max-subtraction needed.
__global__ void k_z(const float* __restrict__ edge) {
    int c = blockIdx.x;
    if (!g_flag[c]) return;
    const float4* row = (const float4*)(edge + (size_t)c * Vn);  // 2500 float4
    const float4* A4 = (const float4*)g_A;
    const float4* B4 = (const float4*)g_Bc;
    int t = threadIdx.x;  // 256
    float s = 0.f;
    int i = t;
    float4 em = (i < 2500) ? row[i] : make_float4(0.f, 0.f, 0.f, 0.f);
    float4 a  = (i < 2500) ? A4[i]  : make_float4(0.f, 0.f, 0.f, 0.f);
    float4 bb = (i < 2500) ? B4[i]  : make_float4(0.f, 0.f, 0.f, 0.f);
    while (i < 2500) {
        int in = i + 256;
        float4 em2, a2, bb2;
        if (in < 2500) { em2 = row[in]; a2 = A4[in]; bb2 = B4[in]; }
        else { em2 = make_float4(0.f,0.f,0.f,0.f); a2 = em2; bb2 = em2; }
        s += __expf(em.x * a.x + (em.x > 0.f ? bb.x : 0.f));
        s += __expf(em.y * a.y + (em.y > 0.f ? bb.y : 0.f));
        s += __expf(em.z * a.z + (em.z > 0.f ? bb.z : 0.f));
        s += __expf(em.w * a.w + (em.w > 0.f ? bb.w : 0.f));
        em = em2; a = a2; bb = bb2;
        i = in;
    }
#pragma unroll
    for (int o = 16; o > 0; o >>= 1) s += __shfl_xor_sync(0xffffffffu, s, o);
    __shared__ float sr[8];
    if ((t & 31) == 0) sr[t >> 5] = s;
    __syncthreads();
    if (t < 8) {
        float x = sr[t];
#pragma unroll
        for (int o = 4; o > 0; o >>= 1) x += __shfl_xor_sync(0xffu, x, o);
        if (t == 0) g_invZ[c] = 1.0f / x;
    }
}

// ------- K6: P[b][v] = sum_l softmax_row(c_bl)[v] / denom_b -------
// grid (20, 64), block 128. Each thread owns one float4 (4 v's). Prefetched.
#define VC 512
__global__ void k_p(const int* __restrict__ list,
                    const int* __restrict__ lens,
                    const float* __restrict__ edge) {
    __shared__ int   sc[Ln];
    __shared__ float siz[Ln];
    int b = blockIdx.y;
    int v0 = blockIdx.x * VC;
    int t = threadIdx.x;
    int len = lens[b];
    if (t < len) {
        int c = list[b * Ln + t];
        sc[t] = c;
        siz[t] = g_invZ[c];
    }
    __syncthreads();

    int vc = min(VC, Vn - v0);
    bool act = (t * 4) < vc;
    int f4 = v0 / 4 + t;  // float4 index into V-sized arrays
    float4 a4 = make_float4(0.f, 0.f, 0.f, 0.f), b4 = a4;
    if (act) {
        a4 = ((const float4*)g_A)[f4];
        b4 = ((const float4*)g_Bc)[f4];
    }
    float4 acc = make_float4(0.f, 0.f, 0.f, 0.f);
    const float4* e4 = (const float4*)edge;

    float4 cur = make_float4(0.f, 0.f, 0.f, 0.f);
    if (len > 0 && act) cur = e4[(size_t)sc[0] * 2500 + f4];
    for (int l = 0; l < len; l++) {
        float4 nxt = make_float4(0.f, 0.f, 0.f, 0.f);
        if (l + 1 < len && act) nxt = e4[(size_t)sc[l + 1] * 2500 + f4];
        float iz = siz[l];
        acc.x += __expf(cur.x * a4.x + (cur.x > 0.f ? b4.x : 0.f)) * iz;
        acc.y += __expf(cur.y * a4.y + (cur.y > 0.f ? b4.y : 0.f)) * iz;
        acc.z += __expf(cur.z * a4.z + (cur.z > 0.f ? b4.z : 0.f)) * iz;
        acc.w += __expf(cur.w * a4.w + (cur.w > 0.f ? b4.w : 0.f)) * iz;
        cur = nxt;
    }
    float invd = 1.0f / (float)(len > 0 ? len : 1);
    acc.x *= invd; acc.y *= invd; acc.z *= invd; acc.w *= invd;
    if (act)
        ((float4*)(g_Pt + (size_t)b * Vn))[f4] = acc;
}

// ------- K7: out[B,300] = P[B,V] @ W[V,300], K-split + atomics -------
#define KT 32
#define DT 32
#define KSPLIT 16
#define KCHUNK 625  // ceil(10000/16)
__global__ void k_out(const float* __restrict__ cw, float* __restrict__ out) {
    int d0 = blockIdx.x * DT;
    int kbeg = blockIdx.y * KCHUNK;
    int kend = min(kbeg + KCHUNK, Vn);
    __shared__ float sP[KT][Bn + 4];
    __shared__ float sW[KT][DT + 4];
    int t = threadIdx.x;     // 128 threads
    int tb = t & 15;         // b quad
    int td = t >> 4;         // d quad
    float acc[4][4];
#pragma unroll
    for (int i = 0; i < 4; i++)
#pragma unroll
        for (int j = 0; j < 4; j++) acc[i][j] = 0.f;

    for (int k0 = kbeg; k0 < kend; k0 += KT) {
        for (int i = t; i < KT * Bn; i += 128) {
            int b = i >> 5, kk = i & 31;  // consecutive kk -> coalesced
            int kv = k0 + kk;
            sP[kk][b] = (kv < kend) ? g_Pt[(size_t)b * Vn + kv] : 0.f;
        }
        for (int i = t; i < KT * DT; i += 128) {
            int kk = i / DT, j = i % DT;
            int kv = k0 + kk, d = d0 + j;
            sW[kk][j] = (kv < kend && d < Dn) ? cw[(size_t)kv * Dn + d] : 0.f;
        }
        __syncthreads();
#pragma unroll 8
        for (int k = 0; k < KT; k++) {
            float p0 = sP[k][tb * 4], p1 = sP[k][tb * 4 + 1];
            float p2 = sP[k][tb * 4 + 2], p3 = sP[k][tb * 4 + 3];
            float w0 = sW[k][td * 4], w1 = sW[k][td * 4 + 1];
            float w2 = sW[k][td * 4 + 2], w3 = sW[k][td * 4 + 3];
            acc[0][0] += p0 * w0; acc[0][1] += p0 * w1; acc[0][2] += p0 * w2; acc[0][3] += p0 * w3;
            acc[1][0] += p1 * w0; acc[1][1] += p1 * w1; acc[1][2] += p1 * w2; acc[1][3] += p1 * w3;
            acc[2][0] += p2 * w0; acc[2][1] += p2 * w1; acc[2][2] += p2 * w2; acc[2][3] += p2 * w3;
            acc[3][0] += p3 * w0; acc[3][1] += p3 * w1; acc[3][2] += p3 * w2; acc[3][3] += p3 * w3;
        }
        __syncthreads();
    }
#pragma unroll
    for (int i = 0; i < 4; i++) {
        int b = tb * 4 + i;
#pragma unroll
        for (int j = 0; j < 4; j++) {
            int d = d0 + td * 4 + j;
            if (d < Dn) atomicAdd(&out[b * Dn + d], acc[i][j]);
        }
    }
}

extern "C" void kernel_launch(void* const* d_in, const int* in_sizes, int n_in,
                              void* d_out, int out_size) {
    const int*   list  = (const int*)d_in[0];
    const int*   lens  = (const int*)d_in[1];
    const float* embed = (const float*)d_in[2];
    const float* cw    = (const float*)d_in[3];
    const float* edge  = (const float*)d_in[4];
    const float* aff   = (const float*)d_in[5];
    const float* lam   = (const float*)d_in[6];
    float* out = (float*)d_out;

    k_zero<<<75, 256>>>(out);
    k_context<<<Bn, 512>>>(list, lens, embed);
    k_reduce_ctx<<<1, 512>>>();
    k_ab<<<(Vn + 7) / 8, 256>>>(cw, aff, lam);
    k_flag<<<(Bn * Ln + 255) / 256, 256>>>(list, lens);
    k_z<<<Vn, 256>>>(edge);
    k_p<<<dim3((Vn + VC - 1) / VC, Bn), 128>>>(list, lens, edge);
    k_out<<<dim3((Dn + DT - 1) / DT, KSPLIT), 128>>>(cw, out);
}